// round 15
// baseline (speedup 1.0000x reference)
#include <cuda_runtime.h>
#include <cuda_fp16.h>
#include <math.h>

// x (32, 1, 720, 1024) f32 -> out (32, 1, 512, 512) f32
// out[z,y,xp] = (pi/720) * sum_v lerp(x[z,0,v,:], t),  t = xf*cos + yf*sin + 511.5
// t in [150.2, 872.8] => always in-bounds for nDct=1024.
//
// R11 = R10 (pre-converted z-oct half sinogram + per-view TMA window staging)
// with the per-view __syncthreads replaced by a 4-deep producer/consumer
// mbarrier pipeline: full[4] (tx, count 1) / empty[4] (count 256). Consumers
// arrive (non-blocking) after each view; only tid0 waits on empty before the
// next cp.async.bulk. Warps decouple by up to 4 views. Trig init merged into
// the convert kernel (one launch fewer).

#define NV   720
#define ND   1024
#define NVND (NV * ND)
#define NXI  512
#define NYI  512
#define WIN  80           // staged window cells per view (16-row tile: span ~67 + slack)
#define RY   4            // r-steps per thread (y stride 4) -> 16 y rows per warp
#define ZC   8            // z-slices per cell
#define WINB (WIN * 16)   // window bytes = 1280
#define NBUF 4

__device__ float g_cos[NV];
__device__ float g_sin[NV];
// z-interleaved half sinogram: [zg][v][d][8z], 4*720*1024*8 half = 47.2 MB
__device__ __align__(16) __half g_hx[4 * NV * ND * 8];

// Convert + transpose: x[z][v][d] f32 -> g_hx[zg][v][d][zz] half (z = zg*8+zz).
// Also initializes the trig tables (block (0,v,0), thread 0).
__global__ __launch_bounds__(256) void convert_kernel(const float* __restrict__ x) {
    const int d  = blockIdx.x * 256 + threadIdx.x;
    const int v  = blockIdx.y;
    const int zg = blockIdx.z;
    if (blockIdx.x == 0 && zg == 0 && threadIdx.x == 0) {
        float th = (float)v * (float)(M_PI / (double)NV);
        g_cos[v] = cosf(th);
        g_sin[v] = sinf(th);
    }
    __half2 h01 = __floats2half2_rn(x[((size_t)(zg * 8 + 0) * NV + v) * ND + d],
                                    x[((size_t)(zg * 8 + 1) * NV + v) * ND + d]);
    __half2 h23 = __floats2half2_rn(x[((size_t)(zg * 8 + 2) * NV + v) * ND + d],
                                    x[((size_t)(zg * 8 + 3) * NV + v) * ND + d]);
    __half2 h45 = __floats2half2_rn(x[((size_t)(zg * 8 + 4) * NV + v) * ND + d],
                                    x[((size_t)(zg * 8 + 5) * NV + v) * ND + d]);
    __half2 h67 = __floats2half2_rn(x[((size_t)(zg * 8 + 6) * NV + v) * ND + d],
                                    x[((size_t)(zg * 8 + 7) * NV + v) * ND + d]);
    uint4 pk;
    pk.x = *reinterpret_cast<unsigned*>(&h01);
    pk.y = *reinterpret_cast<unsigned*>(&h23);
    pk.z = *reinterpret_cast<unsigned*>(&h45);
    pk.w = *reinterpret_cast<unsigned*>(&h67);
    *reinterpret_cast<uint4*>(&g_hx[(((size_t)zg * NV + v) * ND + d) * 8]) = pk;
}

// Must be computed identically by TMA issuer and consumers (same FP ops => it is).
__device__ __forceinline__ int calc_dmin(float c, float s, float xfmin, float yf0) {
    float xsel = (c >= 0.0f) ? xfmin : (xfmin + 63.0f);   // 64-wide x tile
    float tmin = fmaf(xsel, c, fmaf(yf0, s, 511.5f));     // s >= 0 on [0,pi)
    return (int)tmin - 1;                                 // tmin > 0: trunc==floor; -1 ulp guard
}

__device__ __forceinline__ void mbar_wait_acq(unsigned mbar, unsigned phase) {
    unsigned done;
    do {
        asm volatile(
            "{\n\t.reg .pred p;\n\t"
            "mbarrier.try_wait.parity.acquire.cta.shared::cta.b64 p, [%1], %2, 0x989680;\n\t"
            "selp.b32 %0, 1, 0, p;\n\t}"
            : "=r"(done) : "r"(mbar), "r"(phase) : "memory");
    } while (!done);
}

__device__ __forceinline__ void mbar_arrive(unsigned mbar) {
    asm volatile("mbarrier.arrive.shared.b64 _, [%0];" :: "r"(mbar) : "memory");
}

__device__ __forceinline__ void tma_fill(unsigned dst, const __half* src,
                                         unsigned full_mbar) {
    asm volatile("mbarrier.arrive.expect_tx.shared.b64 _, [%0], %1;"
                 :: "r"(full_mbar), "r"((unsigned)WINB) : "memory");
    asm volatile("cp.async.bulk.shared::cta.global.mbarrier::complete_tx::bytes "
                 "[%0], [%1], %2, [%3];"
                 :: "r"(dst), "l"(src), "r"((unsigned)WINB), "r"(full_mbar)
                 : "memory");
}

__global__ __launch_bounds__(256, 4) void backproject_kernel(
    float* __restrict__ out)
{
    __shared__ __align__(16) char cellraw[NBUF][WINB];   // 5 KB
    __shared__ float s_cos[NV], s_sin[NV];               // 5.76 KB
    __shared__ __align__(8) unsigned long long full_mb[NBUF];
    __shared__ __align__(8) unsigned long long empty_mb[NBUF];

    const int tid  = threadIdx.x;            // 256 threads = 8 warps
    const int lane = tid & 31;
    const int wrp  = tid >> 5;
    const int lx   = lane & 7;               // 8 x per warp
    const int ly   = lane >> 3;              // 4 y per warp

    for (int i = tid; i < NV; i += 256) { s_cos[i] = g_cos[i]; s_sin[i] = g_sin[i]; }

    const int xg = blockIdx.x * 64 + wrp * 8 + lx;   // 8 x-tiles of 64
    const int yb = blockIdx.y * 16 + ly;             // 32 y-tiles of 16; thread rows yb + 4r
    const int zg = blockIdx.z;                       // 4 z-octs

    const float xf    = (float)xg - 255.5f;
    const float ybf   = (float)yb - 255.5f;
    const float xfmin = (float)(blockIdx.x * 64) - 255.5f;
    const float yf0   = (float)(blockIdx.y * 16) - 255.5f;

    float acc[RY][ZC];                       // persistent f32 accumulators (32 regs)
#pragma unroll
    for (int r = 0; r < RY; r++)
#pragma unroll
        for (int zz = 0; zz < ZC; zz++) acc[r][zz] = 0.0f;

    unsigned int cell_base, full_base, empty_base;
    asm("{ .reg .u64 t; cvta.to.shared.u64 t, %1; cvt.u32.u64 %0, t; }"
        : "=r"(cell_base) : "l"((const void*)cellraw));
    asm("{ .reg .u64 t; cvta.to.shared.u64 t, %1; cvt.u32.u64 %0, t; }"
        : "=r"(full_base) : "l"((const void*)full_mb));
    asm("{ .reg .u64 t; cvta.to.shared.u64 t, %1; cvt.u32.u64 %0, t; }"
        : "=r"(empty_base) : "l"((const void*)empty_mb));

    const __half* __restrict__ hz = &g_hx[(size_t)zg * NVND * 8];

    if (tid == 0) {
#pragma unroll
        for (int b = 0; b < NBUF; b++) {
            asm volatile("mbarrier.init.shared.b64 [%0], 1;"
                         :: "r"(full_base + b * 8) : "memory");
            asm volatile("mbarrier.init.shared.b64 [%0], 256;"
                         :: "r"(empty_base + b * 8) : "memory");
        }
    }
    __syncthreads();   // trig + mbarrier init visible to all (incl. TMA issues below)

    if (tid == 0) {
        // Prime fills for views 0..3 (no prior consumers; no empty wait).
        // View 0 uses exact (c=1, s=0).
#pragma unroll
        for (int b = 0; b < NBUF; b++) {
            float cb = (b == 0) ? 1.0f : s_cos[b];
            float sb = (b == 0) ? 0.0f : s_sin[b];
            int dm = calc_dmin(cb, sb, xfmin, yf0);
            tma_fill(cell_base + b * WINB, hz + ((size_t)b * ND + dm) * 8,
                     full_base + b * 8);
        }
    }

    for (int v = 0; v < NV; v++) {
        const int buf = v & (NBUF - 1);
        const unsigned phase = (unsigned)((v >> 2) & 1);
        mbar_wait_acq(full_base + buf * 8, phase);

        const float c = (v == 0) ? 1.0f : s_cos[v];
        const float s = (v == 0) ? 0.0f : s_sin[v];
        const int dmin = calc_dmin(c, s, xfmin, yf0);
        // u = t - dmin, in [0, WIN-2) for every pixel of this tile
        float u = fmaf(xf, c, fmaf(ybf, s, 511.5f - (float)dmin));
        const float s4 = 4.0f * s;                 // y stride 4 rows per r-step
        const unsigned int base = cell_base + (unsigned)(buf * WINB);

#pragma unroll
        for (int r = 0; r < RY; r++) {
            int   i0 = (int)u;                     // u > 0: trunc == floor
            float w  = u - (float)i0;
            __half2 wh2 = __float2half2_rn(w);     // one F2FP (broadcast pack)
            unsigned int a0 = base + (unsigned)i0 * 16u;
            uint4 A, B;
            asm("ld.shared.v4.b32 {%0,%1,%2,%3}, [%4];"
                : "=r"(A.x), "=r"(A.y), "=r"(A.z), "=r"(A.w) : "r"(a0));
            asm("ld.shared.v4.b32 {%0,%1,%2,%3}, [%4 + 16];"
                : "=r"(B.x), "=r"(B.y), "=r"(B.z), "=r"(B.w) : "r"(a0));
#pragma unroll
            for (int p = 0; p < 4; p++) {
                unsigned ua = (p == 0) ? A.x : (p == 1) ? A.y : (p == 2) ? A.z : A.w;
                unsigned ub = (p == 0) ? B.x : (p == 1) ? B.y : (p == 2) ? B.z : B.w;
                __half2 ha = *reinterpret_cast<__half2*>(&ua);
                __half2 hb = *reinterpret_cast<__half2*>(&ub);
                // feed-forward half lerp: l = a + w*(b - a); no persistent half state
                __half2 d  = __hsub2(hb, ha);
                __half2 l  = __hfma2(d, wh2, ha);
                float2 f   = __half22float2(l);
                acc[r][2 * p]     += f.x;
                acc[r][2 * p + 1] += f.y;
            }
            u += s4;
        }

        // Non-blocking consumption notice; fast warps run ahead.
        mbar_arrive(empty_base + buf * 8);

        // Producer refills this buffer for view v+4 once all 256 consumed view v.
        if (tid == 0 && v + NBUF < NV) {
            mbar_wait_acq(empty_base + buf * 8, phase);
            float c2 = s_cos[v + NBUF], s2 = s_sin[v + NBUF];
            int dm = calc_dmin(c2, s2, xfmin, yf0);
            tma_fill(base, hz + ((size_t)(v + NBUF) * ND + dm) * 8,
                     full_base + buf * 8);
        }
    }

    const float scale = (float)(M_PI / (double)NV);
#pragma unroll
    for (int r = 0; r < RY; r++) {
        const int y = yb + 4 * r;
#pragma unroll
        for (int zz = 0; zz < ZC; zz++) {
            out[((size_t)(zg * ZC + zz) * NYI + y) * NXI + xg] = acc[r][zz] * scale;
        }
    }
}

extern "C" void kernel_launch(void* const* d_in, const int* in_sizes, int n_in,
                              void* d_out, int out_size)
{
    const float* x   = (const float*)d_in[0];
    float*       out = (float*)d_out;

    convert_kernel<<<dim3(ND / 256, NV, 4), 256>>>(x);

    dim3 grid(8, 32, 4);   // x-tiles, y-tiles, z-octs = 1024 CTAs
    backproject_kernel<<<grid, 256>>>(out);
}